// round 1
// baseline (speedup 1.0000x reference)
#include <cuda_runtime.h>
#include <cstdint>

#define DIN  32
#define DOUT 32

// Packed 2-wide fp32 FMA (Blackwell f32x2 pipe). ptxas will NOT generate this
// from C++ fmaf; inline PTX is required.
__device__ __forceinline__ unsigned long long fma2(unsigned long long a,
                                                   unsigned long long b,
                                                   unsigned long long c) {
    unsigned long long d;
    asm("fma.rn.f32x2 %0, %1, %2, %3;" : "=l"(d) : "l"(a), "l"(b), "l"(c));
    return d;
}

union U64F2 { unsigned long long u; float2 f; };

extern "C" __global__ void __launch_bounds__(256)
layer_relu_kernel(const float* __restrict__ x,
                  const float* __restrict__ W,
                  float* __restrict__ out,
                  int nrows)
{
    // Stage W (32x32 fp32 = 4 KB) into shared; every lane broadcasts from it.
    __shared__ __align__(16) float Ws[DOUT * DIN];
    {
        const float4* Wv = reinterpret_cast<const float4*>(W);
        float4*       Sv = reinterpret_cast<float4*>(Ws);
        int t = threadIdx.x;
        if (t < (DOUT * DIN) / 4) Sv[t] = Wv[t];   // 256 float4
    }
    __syncthreads();

    const int tid    = blockIdx.x * blockDim.x + threadIdx.x;
    const int stride = gridDim.x * blockDim.x;

    for (int row = tid; row < nrows; row += stride) {
        // Load one 128-byte input row as 16 packed f32x2 values (8x LDG.128).
        const ulonglong2* xr =
            reinterpret_cast<const ulonglong2*>(x + (size_t)row * DIN);
        unsigned long long X[16];
        #pragma unroll
        for (int k = 0; k < 8; ++k) {
            ulonglong2 v = __ldg(&xr[k]);
            X[2 * k]     = v.x;
            X[2 * k + 1] = v.y;
        }

        float4* orow = reinterpret_cast<float4*>(out + (size_t)row * DOUT);

        #pragma unroll
        for (int og = 0; og < 8; ++og) {
            float res[4];
            #pragma unroll
            for (int c = 0; c < 4; ++c) {
                const int o = og * 4 + c;
                // W row read as 8x LDS.128 (uniform address -> smem broadcast)
                const ulonglong2* wr =
                    reinterpret_cast<const ulonglong2*>(&Ws[o * DIN]);
                unsigned long long acc = 0ull;   // (+0.f, +0.f)
                #pragma unroll
                for (int k = 0; k < 8; ++k) {
                    ulonglong2 w = wr[k];
                    acc = fma2(X[2 * k],     w.x, acc);
                    acc = fma2(X[2 * k + 1], w.y, acc);
                }
                U64F2 u; u.u = acc;
                float r = u.f.x + u.f.y;
                res[c] = fmaxf(r, 0.0f);
            }
            orow[og] = make_float4(res[0], res[1], res[2], res[3]);
        }
    }
}

extern "C" void kernel_launch(void* const* d_in, const int* in_sizes, int n_in,
                              void* d_out, int out_size) {
    const float* x = (const float*)d_in[0];   // [N, 32] fp32
    const float* W = (const float*)d_in[1];   // [32, 32] fp32
    float* out     = (float*)d_out;           // [N, 32] fp32

    const int nrows = in_sizes[0] / DIN;      // 8388608

    const int threads = 256;
    const int blocks  = 4096;                 // grid-stride: 8 rows/thread
    layer_relu_kernel<<<blocks, threads>>>(x, W, out, nrows);
}

// round 5
// speedup vs baseline: 1.3875x; 1.3875x over previous
#include <cuda_runtime.h>
#include <cstdint>

#define DIN  32
#define DOUT 32
#define RPT  4          // rows per thread: amortizes the W smem broadcast 4x
#define TPB  128        // threads per block

// Packed 2-wide fp32 FMA (Blackwell f32x2 pipe; PTX-only, ptxas never fuses).
__device__ __forceinline__ unsigned long long fma2(unsigned long long a,
                                                   unsigned long long b,
                                                   unsigned long long c) {
    unsigned long long d;
    asm("fma.rn.f32x2 %0, %1, %2, %3;" : "=l"(d) : "l"(a), "l"(b), "l"(c));
    return d;
}

union U64F2 { unsigned long long u; float2 f; };

extern "C" __global__ void __launch_bounds__(TPB, 2)
layer_relu_kernel(const float* __restrict__ x,
                  const float* __restrict__ W,
                  float* __restrict__ out,
                  int nrows)
{
    // Stage W (32x32 fp32 = 4 KB) into shared once per block.
    __shared__ __align__(16) float Ws[DOUT * DIN];
    {
        const float4* Wv = reinterpret_cast<const float4*>(W);
        float4*       Sv = reinterpret_cast<float4*>(Ws);
        #pragma unroll
        for (int i = threadIdx.x; i < (DOUT * DIN) / 4; i += TPB) Sv[i] = Wv[i];
    }
    __syncthreads();

    const long long T    = (long long)gridDim.x * TPB;  // stride between a thread's rows
    const long long gtid = (long long)blockIdx.x * TPB + threadIdx.x;

    // Load RPT full input rows into registers: RPT x 8 LDG.128, high MLP.
    unsigned long long X[RPT][16];
    bool valid[RPT];
    #pragma unroll
    for (int r = 0; r < RPT; ++r) {
        const long long row = gtid + (long long)r * T;
        valid[r] = (row < nrows);
        if (valid[r]) {
            const ulonglong2* xr =
                reinterpret_cast<const ulonglong2*>(x + row * DIN);
            #pragma unroll
            for (int k = 0; k < 8; ++k) {
                ulonglong2 v = __ldg(&xr[k]);
                X[r][2 * k]     = v.x;
                X[r][2 * k + 1] = v.y;
            }
        }
    }

    // Stream W through smem ONCE per RPT rows; 8 output-groups of 4.
    #pragma unroll
    for (int og = 0; og < 8; ++og) {
        float res[RPT][4];
        #pragma unroll
        for (int c = 0; c < 4; ++c) {
            const int o = og * 4 + c;
            const ulonglong2* wr =
                reinterpret_cast<const ulonglong2*>(&Ws[o * DIN]);
            unsigned long long acc[RPT];
            #pragma unroll
            for (int r = 0; r < RPT; ++r) acc[r] = 0ull;
            #pragma unroll
            for (int k = 0; k < 8; ++k) {
                const ulonglong2 w = wr[k];   // 1 LDS.128, reused by RPT rows
                #pragma unroll
                for (int r = 0; r < RPT; ++r) {
                    acc[r] = fma2(X[r][2 * k],     w.x, acc[r]);
                    acc[r] = fma2(X[r][2 * k + 1], w.y, acc[r]);
                }
            }
            #pragma unroll
            for (int r = 0; r < RPT; ++r) {
                U64F2 u; u.u = acc[r];
                res[r][c] = fmaxf(u.f.x + u.f.y, 0.0f);
            }
        }
        #pragma unroll
        for (int r = 0; r < RPT; ++r) {
            const long long row = gtid + (long long)r * T;
            if (valid[r]) {
                float4* orow = reinterpret_cast<float4*>(out + row * DOUT);
                orow[og] = make_float4(res[r][0], res[r][1], res[r][2], res[r][3]);
            }
        }
    }
}

extern "C" void kernel_launch(void* const* d_in, const int* in_sizes, int n_in,
                              void* d_out, int out_size) {
    const float* x = (const float*)d_in[0];   // [N, 32] fp32
    const float* W = (const float*)d_in[1];   // [32, 32] fp32
    float* out     = (float*)d_out;           // [N, 32] fp32

    const int nrows = in_sizes[0] / DIN;      // 8388608

    const int rows_per_block = TPB * RPT;     // 512
    const int blocks = (nrows + rows_per_block - 1) / rows_per_block;  // 16384
    layer_relu_kernel<<<blocks, TPB>>>(x, W, out, nrows);
}